// round 10
// baseline (speedup 1.0000x reference)
#include <cuda_runtime.h>
#include <cuda_fp16.h>
#include <cstdint>
#include <math.h>

// BatchHardTripletLoss: N=8192, D=128, fp32 in, scalar fp32 out.
// Gram on mma.sync fp16 (fp32 acc), single pass: dot = fp16(x)_i . fp16(x)_j
// Upper-triangle 128x128 tiles (2080 CTAs, 1 tile each); dual fold:
//   row-fold: anchors i, tv = cj[j] - 2 dot -> slot (bj, sub=wn)   [shfl]
//   col-fold: anchors j, tv = cj[i] - 2 dot -> slot (bi, sub=2)    [smem]
// 3 CTAs/SM (67.5KB smem, regs capped ~85 via launch_bounds(256,3));
// B fragments loaded 2-at-a-time in the k-loop to keep peak regs at the cap
// with all 64 accumulators register-resident.
// Col-fold scratch aliases the dead B tile after the k-loop.

#define NPTS   8192
#define DIM    128
#define MARGIN 0.2f
#define EPSV   1e-6f
#define TILE   128
#define NCTAS  2080              // 64*65/2
#define NSUB   3

// smem layout (bytes)
#define OFF_A    0               // 32 KB fp16 A tile
#define OFF_B    32768           // 32 KB fp16 B tile (scratch aliases after k-loop)
#define OFF_CJR  65536           // float2[128] row meta (cj, label)
#define OFF_CJC  66560           // float2[128] col meta
#define SMEM_BYTES 67584
#define SCR_STRIDE 18            // 16 groups + pad -> conflict-free
#define SCR_HN_OFF (128 * SCR_STRIDE * 4)   // 9216 B

__device__ float g_ci[NPTS];
__device__ float g_cj[NPTS];
__device__ __align__(16) __half g_xh[NPTS * DIM];
__device__ float g_php[64 * NSUB * NPTS];
__device__ float g_phn[64 * NSUB * NPTS];
__device__ float g_bsum[64];
__device__ int   g_cnt = 0;

// ---------------- helpers ----------------
__device__ __forceinline__ uint32_t smem_u32(const void* p) {
    uint32_t a;
    asm("{ .reg .u64 t; cvta.to.shared.u64 t, %1; cvt.u32.u64 %0, t; }" : "=r"(a) : "l"(p));
    return a;
}
// swizzled offset of 16B chunk c (0..15) in row r (0..127), 128x128 f16 tile
__device__ __forceinline__ uint32_t t_off(int r, int c) {
    return (uint32_t)(((r >> 3) << 10) + ((c >> 3) << 14) + ((r & 7) << 7)
                      + (((c & 7) ^ (r & 7)) << 4));
}
__device__ __forceinline__ void cp16(uint32_t saddr, const void* gaddr) {
    asm volatile("cp.async.cg.shared.global [%0], [%1], 16;"
                 :: "r"(saddr), "l"(gaddr) : "memory");
}
__device__ __forceinline__ void ldsm4(uint32_t* r, uint32_t addr) {
    asm volatile("ldmatrix.sync.aligned.m8n8.x4.shared.b16 {%0,%1,%2,%3}, [%4];"
                 : "=r"(r[0]), "=r"(r[1]), "=r"(r[2]), "=r"(r[3]) : "r"(addr));
}
__device__ __forceinline__ void mma16816(float* c, const uint32_t* a, const uint32_t* b) {
    asm volatile("mma.sync.aligned.m16n8k16.row.col.f32.f16.f16.f32 "
                 "{%0,%1,%2,%3}, {%4,%5,%6,%7}, {%8,%9}, {%0,%1,%2,%3};"
                 : "+f"(c[0]), "+f"(c[1]), "+f"(c[2]), "+f"(c[3])
                 : "r"(a[0]), "r"(a[1]), "r"(a[2]), "r"(a[3]), "r"(b[0]), "r"(b[1]));
}
__device__ __forceinline__ int strip_base(int b) { return b * (129 - b) / 2; }

// ---------------- precompute: ci/cj + fp16 conversion, 4 rows/warp -------
__global__ void precompute_kernel(const float* __restrict__ x) {
    int w = (blockIdx.x * blockDim.x + threadIdx.x) >> 5;
    int lane = threadIdx.x & 31;
    int row0 = w * 4;
    float4 v[4];
    #pragma unroll
    for (int r = 0; r < 4; r++)
        v[r] = *(const float4*)(x + (size_t)(row0 + r) * DIM + lane * 4);
    #pragma unroll
    for (int r = 0; r < 4; r++) {
        int row = row0 + r;
        float sq = v[r].x * v[r].x + v[r].y * v[r].y + v[r].z * v[r].z + v[r].w * v[r].w;
        float s  = v[r].x + v[r].y + v[r].z + v[r].w;
        #pragma unroll
        for (int o = 16; o; o >>= 1) {
            sq += __shfl_xor_sync(0xffffffffu, sq, o);
            s  += __shfl_xor_sync(0xffffffffu, s,  o);
        }
        if (lane == 0) {
            g_ci[row] = sq - 2.0f * EPSV * s;
            g_cj[row] = sq + 2.0f * EPSV * s + (float)DIM * EPSV * EPSV;
        }
        __half2* dh = (__half2*)(g_xh + (size_t)row * DIM + lane * 4);
        dh[0] = __floats2half2_rn(v[r].x, v[r].y);
        dh[1] = __floats2half2_rn(v[r].z, v[r].w);
    }
}

// ---------------- main fused kernel: one triangle tile per CTA ----------
__global__ void __launch_bounds__(256, 3)
tile_kernel(const int* __restrict__ tgt) {
    extern __shared__ char smem[];
    const uint32_t sb = smem_u32(smem);
    const int tid  = threadIdx.x;
    const int lane = tid & 31;
    const int wid  = tid >> 5;
    const int wm = wid & 3;          // 4 warps over M (32 rows each)
    const int wn = wid >> 2;         // 2 warps over N (64 cols each)
    float2* scjr = (float2*)(smem + OFF_CJR);
    float2* scjc = (float2*)(smem + OFF_CJC);

    // (bi, bj) from linear upper-triangle index
    const int t = blockIdx.x;
    int bi = (int)(64.5f - sqrtf(64.5f * 64.5f - 2.0f * (float)t));
    if (bi < 0) bi = 0; if (bi > 63) bi = 63;
    while (bi < 63 && strip_base(bi + 1) <= t) bi++;
    while (bi > 0 && strip_base(bi) > t) bi--;
    const int bj = bi + (t - strip_base(bi));

    // stage A (32 KB) + B (32 KB) + meta
    {
        const char* ga = (const char*)(g_xh + (size_t)bi * TILE * DIM);
        const char* gb = (const char*)(g_xh + (size_t)bj * TILE * DIM);
        #pragma unroll
        for (int it = 0; it < 8; it++) {
            int lin = it * 256 + tid;
            uint32_t off = t_off(lin >> 4, lin & 15);
            cp16(sb + OFF_A + off, ga + (size_t)lin * 16);
            cp16(sb + OFF_B + off, gb + (size_t)lin * 16);
        }
        if (tid < TILE) {
            int r = bi * TILE + tid;
            int j = bj * TILE + tid;
            scjr[tid] = make_float2(g_cj[r], __int_as_float(tgt[r]));
            scjc[tid] = make_float2(g_cj[j], __int_as_float(tgt[j]));
        }
        asm volatile("cp.async.commit_group;" ::: "memory");
    }

    const int ra_lane = (lane & 15);
    const int ca_add  = (lane >> 4);
    const int rb_lane = ((lane >> 4) << 3) + (lane & 7);
    const int cb_add  = ((lane >> 3) & 1);

    asm volatile("cp.async.wait_group 0;" ::: "memory");
    __syncthreads();

    // ---------------- single-pass MMA over K=128 ----------------
    const uint32_t sA = sb + OFF_A, sB = sb + OFF_B;

    float acc[2][8][4];
    #pragma unroll
    for (int mt = 0; mt < 2; mt++)
        #pragma unroll
        for (int n8 = 0; n8 < 8; n8++)
            #pragma unroll
            for (int q = 0; q < 4; q++) acc[mt][n8][q] = 0.0f;

    #pragma unroll
    for (int ks = 0; ks < 8; ks++) {
        uint32_t ah[2][4];
        #pragma unroll
        for (int mt = 0; mt < 2; mt++) {
            uint32_t off = t_off(wm * 32 + mt * 16 + ra_lane, 2 * ks + ca_add);
            ldsm4(ah[mt], sA + off);
        }
        // B fragments in two halves: bh[2][4] live (8 regs) instead of 16
        #pragma unroll
        for (int half = 0; half < 2; half++) {
            uint32_t bh[2][4];
            #pragma unroll
            for (int nt2 = 0; nt2 < 2; nt2++) {
                int nt = half * 2 + nt2;
                uint32_t off = t_off(wn * 64 + nt * 16 + rb_lane, 2 * ks + cb_add);
                ldsm4(bh[nt2], sB + off);
            }
            #pragma unroll
            for (int mt = 0; mt < 2; mt++)
                #pragma unroll
                for (int nt2 = 0; nt2 < 2; nt2++) {
                    int nt = half * 2 + nt2;
                    mma16816(acc[mt][2 * nt],     ah[mt], &bh[nt2][0]);
                    mma16816(acc[mt][2 * nt + 1], ah[mt], &bh[nt2][2]);
                }
        }
    }

    __syncthreads();   // all warps done with B before scratch aliasing

    // ---------------- dual-fold epilogue ----------------
    float cjr[2][2];
    int   tir[2][2];
    #pragma unroll
    for (int mt = 0; mt < 2; mt++)
        #pragma unroll
        for (int so = 0; so < 2; so++) {
            float2 q = scjr[wm * 32 + mt * 16 + so * 8 + (lane >> 2)];
            cjr[mt][so] = q.x;
            tir[mt][so] = __float_as_int(q.y);
        }
    float hpr[2][2], hnr[2][2];
    #pragma unroll
    for (int mt = 0; mt < 2; mt++)
        #pragma unroll
        for (int so = 0; so < 2; so++) { hpr[mt][so] = -3.4e38f; hnr[mt][so] = 3.4e38f; }

    // col-fold scratch over dead B tile: [128 cols][18] per array
    float* scrHp = (float*)(smem + OFF_B);
    float* scrHn = (float*)(smem + OFF_B + SCR_HN_OFF);
    const int g16 = wm * 4 + (lane >> 3);          // group after 1-round shfl fold
    const bool keep = ((lane >> 2) & 1) == 0;

    #pragma unroll
    for (int n8 = 0; n8 < 8; n8++) {
        #pragma unroll
        for (int par = 0; par < 2; par++) {
            const int colL = wn * 64 + n8 * 8 + (lane & 3) * 2 + par;
            float2 qc = scjc[colL];
            float cjc = qc.x;
            int   tjc = __float_as_int(qc.y);
            float hpc = -3.4e38f, hnc = 3.4e38f;
            #pragma unroll
            for (int mt = 0; mt < 2; mt++)
                #pragma unroll
                for (int so = 0; so < 2; so++) {
                    float d = -2.0f * acc[mt][n8][so * 2 + par];
                    float tvr = d + cjc;
                    float tvc = d + cjr[mt][so];
                    if (tjc == tir[mt][so]) {
                        hpr[mt][so] = fmaxf(hpr[mt][so], tvr);
                        hpc         = fmaxf(hpc,         tvc);
                    } else {
                        hnr[mt][so] = fminf(hnr[mt][so], tvr);
                        hnc         = fminf(hnc,         tvc);
                    }
                }
            // fold group pairs (lane>>2 even/odd) before scratch
            hpc = fmaxf(hpc, __shfl_xor_sync(0xffffffffu, hpc, 4));
            hnc = fminf(hnc, __shfl_xor_sync(0xffffffffu, hnc, 4));
            if (keep) {
                scrHp[colL * SCR_STRIDE + g16] = hpc;
                scrHn[colL * SCR_STRIDE + g16] = hnc;
            }
        }
    }

    // row fold across the 4 column-lanes, write slot (bj, sub=wn)
    #pragma unroll
    for (int o = 1; o <= 2; o <<= 1)
        #pragma unroll
        for (int mt = 0; mt < 2; mt++)
            #pragma unroll
            for (int so = 0; so < 2; so++) {
                hpr[mt][so] = fmaxf(hpr[mt][so], __shfl_xor_sync(0xffffffffu, hpr[mt][so], o));
                hnr[mt][so] = fminf(hnr[mt][so], __shfl_xor_sync(0xffffffffu, hnr[mt][so], o));
            }
    if ((lane & 3) == 0) {
        #pragma unroll
        for (int mt = 0; mt < 2; mt++)
            #pragma unroll
            for (int so = 0; so < 2; so++) {
                int r = bi * TILE + wm * 32 + mt * 16 + so * 8 + (lane >> 2);
                g_php[((bj * NSUB) + wn) * NPTS + r] = hpr[mt][so];
                g_phn[((bj * NSUB) + wn) * NPTS + r] = hnr[mt][so];
            }
    }

    __syncthreads();   // scratch fully written

    // col fold: tid<128 folds hp for column tid; tid>=128 folds hn
    {
        int colL = tid & 127;
        const float* src = (tid < 128) ? scrHp : scrHn;
        float v = src[colL * SCR_STRIDE];
        if (tid < 128) {
            #pragma unroll
            for (int gq = 1; gq < 16; gq++) v = fmaxf(v, src[colL * SCR_STRIDE + gq]);
            g_php[((bi * NSUB) + 2) * NPTS + bj * TILE + colL] = v;
        } else {
            #pragma unroll
            for (int gq = 1; gq < 16; gq++) v = fminf(v, src[colL * SCR_STRIDE + gq]);
            g_phn[((bi * NSUB) + 2) * NPTS + bj * TILE + colL] = v;
        }
    }
}

// ---------------- fused merge: slots -> loss -> mean (last block done) ----
__global__ void merge_kernel(float* __restrict__ out) {
    __shared__ float ssum[128];
    __shared__ float sfin[2];
    __shared__ bool  last;
    int r = blockIdx.x * 128 + threadIdx.x;
    int blk = r >> 7;
    float hp = -3.4e38f, hn = 3.4e38f;
    for (int o = 0; o < 64; o++) {
        const float* php = g_php + (size_t)o * NSUB * NPTS + r;
        const float* phn = g_phn + (size_t)o * NSUB * NPTS + r;
        if (o >= blk) {
            hp = fmaxf(hp, fmaxf(php[0], php[(size_t)NPTS]));
            hn = fminf(hn, fminf(phn[0], phn[(size_t)NPTS]));
        }
        if (o <= blk) {
            hp = fmaxf(hp, php[2 * (size_t)NPTS]);
            hn = fminf(hn, phn[2 * (size_t)NPTS]);
        }
    }
    float ci = g_ci[r];
    float hpd = sqrtf(fmaxf(ci + hp, 0.0f));
    float hnd = sqrtf(fmaxf(ci + hn, 0.0f));
    ssum[threadIdx.x] = fmaxf(hpd - hnd + MARGIN, 0.0f);
    __syncthreads();
    for (int o = 64; o; o >>= 1) {
        if (threadIdx.x < o) ssum[threadIdx.x] += ssum[threadIdx.x + o];
        __syncthreads();
    }
    if (threadIdx.x == 0) {
        g_bsum[blockIdx.x] = ssum[0];
        __threadfence();
        int prev = atomicAdd(&g_cnt, 1);
        last = (prev == gridDim.x - 1);
    }
    __syncthreads();
    if (last) {
        if (threadIdx.x < 64) {
            float v = g_bsum[threadIdx.x];
            #pragma unroll
            for (int o = 16; o; o >>= 1) v += __shfl_xor_sync(0xffffffffu, v, o);
            if ((threadIdx.x & 31) == 0) sfin[threadIdx.x >> 5] = v;
        }
        __syncthreads();
        if (threadIdx.x == 0) {
            out[0] = (sfin[0] + sfin[1]) / (float)NPTS;
            g_cnt = 0;   // reset for next graph replay
        }
    }
}

extern "C" void kernel_launch(void* const* d_in, const int* in_sizes, int n_in,
                              void* d_out, int out_size) {
    const float* x   = (const float*)d_in[0];
    const int*   tgt = (const int*)d_in[1];
    float*       out = (float*)d_out;

    precompute_kernel<<<256, 256>>>(x);

    cudaFuncSetAttribute(tile_kernel,
                         cudaFuncAttributeMaxDynamicSharedMemorySize, SMEM_BYTES);
    tile_kernel<<<NCTAS, 256, SMEM_BYTES>>>(tgt);

    merge_kernel<<<NPTS / 128, 128>>>(out);
}

// round 11
// speedup vs baseline: 1.8227x; 1.8227x over previous
#include <cuda_runtime.h>
#include <cuda_fp16.h>
#include <cstdint>
#include <math.h>

// BatchHardTripletLoss: N=8192, D=128, fp32 in, scalar fp32 out.
// Gram on mma.sync fp16 (fp32 acc), single pass: dot = fp16(x)_i . fp16(x)_j
// Upper-triangle 128x128 tiles (2080 CTAs, 1 tile each); dual fold:
//   row-fold: anchors i, tv = cj[j] - 2 dot -> slot (bj, sub=wn)   [shfl]
//   col-fold: anchors j, tv = cj[i] - 2 dot -> slot (bi, sub=2)    [smem]
// 2 CTAs/SM (67.5KB smem). Epilogue arithmetic packed with f32x2 FFMA2:
//   (tv0,tv1) = fma.rn.f32x2((acc0,acc1), (-2,-2), (c0,c1)) — one issue
// for each pair of adjacent columns, on both fold sides.
// Col-fold scratch aliases the dead B tile after the k-loop.

#define NPTS   8192
#define DIM    128
#define MARGIN 0.2f
#define EPSV   1e-6f
#define TILE   128
#define NCTAS  2080              // 64*65/2
#define NSUB   3

// smem layout (bytes)
#define OFF_A    0               // 32 KB fp16 A tile
#define OFF_B    32768           // 32 KB fp16 B tile (scratch aliases after k-loop)
#define OFF_CJR  65536           // float2[128] row meta (cj, label)
#define OFF_CJC  66560           // float2[128] col meta
#define SMEM_BYTES 67584
#define SCR_STRIDE 18            // 16 groups + pad -> conflict-free
#define SCR_HN_OFF (128 * SCR_STRIDE * 4)   // 9216 B

__device__ float g_ci[NPTS];
__device__ float g_cj[NPTS];
__device__ __align__(16) __half g_xh[NPTS * DIM];
__device__ float g_php[64 * NSUB * NPTS];
__device__ float g_phn[64 * NSUB * NPTS];
__device__ float g_bsum[64];
__device__ int   g_cnt = 0;

// ---------------- helpers ----------------
__device__ __forceinline__ uint32_t smem_u32(const void* p) {
    uint32_t a;
    asm("{ .reg .u64 t; cvta.to.shared.u64 t, %1; cvt.u32.u64 %0, t; }" : "=r"(a) : "l"(p));
    return a;
}
// swizzled offset of 16B chunk c (0..15) in row r (0..127), 128x128 f16 tile
__device__ __forceinline__ uint32_t t_off(int r, int c) {
    return (uint32_t)(((r >> 3) << 10) + ((c >> 3) << 14) + ((r & 7) << 7)
                      + (((c & 7) ^ (r & 7)) << 4));
}
__device__ __forceinline__ void cp16(uint32_t saddr, const void* gaddr) {
    asm volatile("cp.async.cg.shared.global [%0], [%1], 16;"
                 :: "r"(saddr), "l"(gaddr) : "memory");
}
__device__ __forceinline__ void ldsm4(uint32_t* r, uint32_t addr) {
    asm volatile("ldmatrix.sync.aligned.m8n8.x4.shared.b16 {%0,%1,%2,%3}, [%4];"
                 : "=r"(r[0]), "=r"(r[1]), "=r"(r[2]), "=r"(r[3]) : "r"(addr));
}
__device__ __forceinline__ void mma16816(float* c, const uint32_t* a, const uint32_t* b) {
    asm volatile("mma.sync.aligned.m16n8k16.row.col.f32.f16.f16.f32 "
                 "{%0,%1,%2,%3}, {%4,%5,%6,%7}, {%8,%9}, {%0,%1,%2,%3};"
                 : "+f"(c[0]), "+f"(c[1]), "+f"(c[2]), "+f"(c[3])
                 : "r"(a[0]), "r"(a[1]), "r"(a[2]), "r"(a[3]), "r"(b[0]), "r"(b[1]));
}
// packed f32x2 helpers (sm_100-family ISA; SASS FFMA2)
__device__ __forceinline__ uint64_t pack2(float lo, float hi) {
    uint64_t r;
    asm("mov.b64 %0, {%1, %2};" : "=l"(r) : "f"(lo), "f"(hi));
    return r;
}
__device__ __forceinline__ void unpack2(float& lo, float& hi, uint64_t v) {
    asm("mov.b64 {%0, %1}, %2;" : "=f"(lo), "=f"(hi) : "l"(v));
}
__device__ __forceinline__ uint64_t fma2(uint64_t a, uint64_t b, uint64_t c) {
    uint64_t d;
    asm("fma.rn.f32x2 %0, %1, %2, %3;" : "=l"(d) : "l"(a), "l"(b), "l"(c));
    return d;
}
__device__ __forceinline__ int strip_base(int b) { return b * (129 - b) / 2; }

// ---------------- precompute: ci/cj + fp16 conversion (2 rows/warp) ------
__global__ void precompute_kernel(const float* __restrict__ x) {
    int w = (blockIdx.x * blockDim.x + threadIdx.x) >> 5;
    int lane = threadIdx.x & 31;
    int row0 = w * 2;
    float4 v0 = *(const float4*)(x + (size_t)row0 * DIM + lane * 4);
    float4 v1 = *(const float4*)(x + (size_t)(row0 + 1) * DIM + lane * 4);
    #pragma unroll
    for (int r = 0; r < 2; r++) {
        float4 v = r ? v1 : v0;
        int row = row0 + r;
        float sq = v.x * v.x + v.y * v.y + v.z * v.z + v.w * v.w;
        float s  = v.x + v.y + v.z + v.w;
        #pragma unroll
        for (int o = 16; o; o >>= 1) {
            sq += __shfl_xor_sync(0xffffffffu, sq, o);
            s  += __shfl_xor_sync(0xffffffffu, s,  o);
        }
        if (lane == 0) {
            g_ci[row] = sq - 2.0f * EPSV * s;
            g_cj[row] = sq + 2.0f * EPSV * s + (float)DIM * EPSV * EPSV;
        }
        __half2* dh = (__half2*)(g_xh + (size_t)row * DIM + lane * 4);
        dh[0] = __floats2half2_rn(v.x, v.y);
        dh[1] = __floats2half2_rn(v.z, v.w);
    }
}

// ---------------- main fused kernel: one triangle tile per CTA ----------
__global__ void __launch_bounds__(256, 2)
tile_kernel(const int* __restrict__ tgt) {
    extern __shared__ char smem[];
    const uint32_t sb = smem_u32(smem);
    const int tid  = threadIdx.x;
    const int lane = tid & 31;
    const int wid  = tid >> 5;
    const int wm = wid & 3;          // 4 warps over M (32 rows each)
    const int wn = wid >> 2;         // 2 warps over N (64 cols each)
    float2* scjr = (float2*)(smem + OFF_CJR);
    float2* scjc = (float2*)(smem + OFF_CJC);

    // (bi, bj) from linear upper-triangle index
    const int t = blockIdx.x;
    int bi = (int)(64.5f - sqrtf(64.5f * 64.5f - 2.0f * (float)t));
    if (bi < 0) bi = 0; if (bi > 63) bi = 63;
    while (bi < 63 && strip_base(bi + 1) <= t) bi++;
    while (bi > 0 && strip_base(bi) > t) bi--;
    const int bj = bi + (t - strip_base(bi));

    // stage A (32 KB) + B (32 KB) + meta
    {
        const char* ga = (const char*)(g_xh + (size_t)bi * TILE * DIM);
        const char* gb = (const char*)(g_xh + (size_t)bj * TILE * DIM);
        #pragma unroll
        for (int it = 0; it < 8; it++) {
            int lin = it * 256 + tid;
            uint32_t off = t_off(lin >> 4, lin & 15);
            cp16(sb + OFF_A + off, ga + (size_t)lin * 16);
            cp16(sb + OFF_B + off, gb + (size_t)lin * 16);
        }
        if (tid < TILE) {
            int r = bi * TILE + tid;
            int j = bj * TILE + tid;
            scjr[tid] = make_float2(g_cj[r], __int_as_float(tgt[r]));
            scjc[tid] = make_float2(g_cj[j], __int_as_float(tgt[j]));
        }
        asm volatile("cp.async.commit_group;" ::: "memory");
    }

    const int ra_lane = (lane & 15);
    const int ca_add  = (lane >> 4);
    const int rb_lane = ((lane >> 4) << 3) + (lane & 7);
    const int cb_add  = ((lane >> 3) & 1);

    asm volatile("cp.async.wait_group 0;" ::: "memory");
    __syncthreads();

    // ---------------- single-pass MMA over K=128 ----------------
    const uint32_t sA = sb + OFF_A, sB = sb + OFF_B;

    float acc[2][8][4];
    #pragma unroll
    for (int mt = 0; mt < 2; mt++)
        #pragma unroll
        for (int n8 = 0; n8 < 8; n8++)
            #pragma unroll
            for (int q = 0; q < 4; q++) acc[mt][n8][q] = 0.0f;

    #pragma unroll
    for (int ks = 0; ks < 8; ks++) {
        uint32_t ah[2][4], bh[4][4];
        #pragma unroll
        for (int mt = 0; mt < 2; mt++) {
            uint32_t off = t_off(wm * 32 + mt * 16 + ra_lane, 2 * ks + ca_add);
            ldsm4(ah[mt], sA + off);
        }
        #pragma unroll
        for (int nt = 0; nt < 4; nt++) {
            uint32_t off = t_off(wn * 64 + nt * 16 + rb_lane, 2 * ks + cb_add);
            ldsm4(bh[nt], sB + off);
        }
        #pragma unroll
        for (int mt = 0; mt < 2; mt++)
            #pragma unroll
            for (int nt = 0; nt < 4; nt++) {
                mma16816(acc[mt][2 * nt],     ah[mt], &bh[nt][0]);
                mma16816(acc[mt][2 * nt + 1], ah[mt], &bh[nt][2]);
            }
    }

    __syncthreads();   // all warps done with B before scratch aliasing

    // ---------------- dual-fold epilogue (packed f32x2) ----------------
    const uint64_t NEG2 = pack2(-2.0f, -2.0f);
    uint64_t cjr2[2][2];
    int      tir[2][2];
    #pragma unroll
    for (int mt = 0; mt < 2; mt++)
        #pragma unroll
        for (int so = 0; so < 2; so++) {
            float2 q = scjr[wm * 32 + mt * 16 + so * 8 + (lane >> 2)];
            cjr2[mt][so] = pack2(q.x, q.x);
            tir[mt][so] = __float_as_int(q.y);
        }
    float hpr[2][2], hnr[2][2];
    #pragma unroll
    for (int mt = 0; mt < 2; mt++)
        #pragma unroll
        for (int so = 0; so < 2; so++) { hpr[mt][so] = -3.4e38f; hnr[mt][so] = 3.4e38f; }

    // col-fold scratch over dead B tile: [128 cols][18] per array
    float* scrHp = (float*)(smem + OFF_B);
    float* scrHn = (float*)(smem + OFF_B + SCR_HN_OFF);
    const int g16 = wm * 4 + (lane >> 3);          // group after 1-round shfl fold
    const bool keep = ((lane >> 2) & 1) == 0;

    #pragma unroll
    for (int n8 = 0; n8 < 8; n8++) {
        const int col0 = wn * 64 + n8 * 8 + (lane & 3) * 2;
        float2 qc0 = scjc[col0];
        float2 qc1 = scjc[col0 + 1];
        const uint64_t cjc2 = pack2(qc0.x, qc1.x);
        const int tj0 = __float_as_int(qc0.y);
        const int tj1 = __float_as_int(qc1.y);
        float hpc0 = -3.4e38f, hnc0 = 3.4e38f;
        float hpc1 = -3.4e38f, hnc1 = 3.4e38f;
        #pragma unroll
        for (int mt = 0; mt < 2; mt++)
            #pragma unroll
            for (int so = 0; so < 2; so++) {
                uint64_t accp = pack2(acc[mt][n8][so * 2], acc[mt][n8][so * 2 + 1]);
                uint64_t tvr2 = fma2(accp, NEG2, cjc2);          // (d0+cjc0, d1+cjc1)
                uint64_t tvc2 = fma2(accp, NEG2, cjr2[mt][so]);  // (d0+cjr,  d1+cjr)
                float r0, r1, c0, c1;
                unpack2(r0, r1, tvr2);
                unpack2(c0, c1, tvc2);
                if (tj0 == tir[mt][so]) { hpr[mt][so] = fmaxf(hpr[mt][so], r0); hpc0 = fmaxf(hpc0, c0); }
                else                    { hnr[mt][so] = fminf(hnr[mt][so], r0); hnc0 = fminf(hnc0, c0); }
                if (tj1 == tir[mt][so]) { hpr[mt][so] = fmaxf(hpr[mt][so], r1); hpc1 = fmaxf(hpc1, c1); }
                else                    { hnr[mt][so] = fminf(hnr[mt][so], r1); hnc1 = fminf(hnc1, c1); }
            }
        // fold group pairs (lane>>2 even/odd) before scratch
        hpc0 = fmaxf(hpc0, __shfl_xor_sync(0xffffffffu, hpc0, 4));
        hnc0 = fminf(hnc0, __shfl_xor_sync(0xffffffffu, hnc0, 4));
        hpc1 = fmaxf(hpc1, __shfl_xor_sync(0xffffffffu, hpc1, 4));
        hnc1 = fminf(hnc1, __shfl_xor_sync(0xffffffffu, hnc1, 4));
        if (keep) {
            scrHp[col0 * SCR_STRIDE + g16] = hpc0;
            scrHn[col0 * SCR_STRIDE + g16] = hnc0;
            scrHp[(col0 + 1) * SCR_STRIDE + g16] = hpc1;
            scrHn[(col0 + 1) * SCR_STRIDE + g16] = hnc1;
        }
    }

    // row fold across the 4 column-lanes, write slot (bj, sub=wn)
    #pragma unroll
    for (int o = 1; o <= 2; o <<= 1)
        #pragma unroll
        for (int mt = 0; mt < 2; mt++)
            #pragma unroll
            for (int so = 0; so < 2; so++) {
                hpr[mt][so] = fmaxf(hpr[mt][so], __shfl_xor_sync(0xffffffffu, hpr[mt][so], o));
                hnr[mt][so] = fminf(hnr[mt][so], __shfl_xor_sync(0xffffffffu, hnr[mt][so], o));
            }
    if ((lane & 3) == 0) {
        #pragma unroll
        for (int mt = 0; mt < 2; mt++)
            #pragma unroll
            for (int so = 0; so < 2; so++) {
                int r = bi * TILE + wm * 32 + mt * 16 + so * 8 + (lane >> 2);
                g_php[((bj * NSUB) + wn) * NPTS + r] = hpr[mt][so];
                g_phn[((bj * NSUB) + wn) * NPTS + r] = hnr[mt][so];
            }
    }

    __syncthreads();   // scratch fully written

    // col fold: tid<128 folds hp for column tid; tid>=128 folds hn
    {
        int colL = tid & 127;
        const float* src = (tid < 128) ? scrHp : scrHn;
        float v = src[colL * SCR_STRIDE];
        if (tid < 128) {
            #pragma unroll
            for (int gq = 1; gq < 16; gq++) v = fmaxf(v, src[colL * SCR_STRIDE + gq]);
            g_php[((bi * NSUB) + 2) * NPTS + bj * TILE + colL] = v;
        } else {
            #pragma unroll
            for (int gq = 1; gq < 16; gq++) v = fminf(v, src[colL * SCR_STRIDE + gq]);
            g_phn[((bi * NSUB) + 2) * NPTS + bj * TILE + colL] = v;
        }
    }
}

// ---------------- fused merge: slots -> loss -> mean (last block done) ----
__global__ void merge_kernel(float* __restrict__ out) {
    __shared__ float ssum[128];
    __shared__ float sfin[2];
    __shared__ bool  last;
    int r = blockIdx.x * 128 + threadIdx.x;
    int blk = r >> 7;
    float hp = -3.4e38f, hn = 3.4e38f;
    for (int o = 0; o < 64; o++) {
        const float* php = g_php + (size_t)o * NSUB * NPTS + r;
        const float* phn = g_phn + (size_t)o * NSUB * NPTS + r;
        if (o >= blk) {
            hp = fmaxf(hp, fmaxf(php[0], php[(size_t)NPTS]));
            hn = fminf(hn, fminf(phn[0], phn[(size_t)NPTS]));
        }
        if (o <= blk) {
            hp = fmaxf(hp, php[2 * (size_t)NPTS]);
            hn = fminf(hn, phn[2 * (size_t)NPTS]);
        }
    }
    float ci = g_ci[r];
    float hpd = sqrtf(fmaxf(ci + hp, 0.0f));
    float hnd = sqrtf(fmaxf(ci + hn, 0.0f));
    ssum[threadIdx.x] = fmaxf(hpd - hnd + MARGIN, 0.0f);
    __syncthreads();
    for (int o = 64; o; o >>= 1) {
        if (threadIdx.x < o) ssum[threadIdx.x] += ssum[threadIdx.x + o];
        __syncthreads();
    }
    if (threadIdx.x == 0) {
        g_bsum[blockIdx.x] = ssum[0];
        __threadfence();
        int prev = atomicAdd(&g_cnt, 1);
        last = (prev == gridDim.x - 1);
    }
    __syncthreads();
    if (last) {
        if (threadIdx.x < 64) {
            float v = g_bsum[threadIdx.x];
            #pragma unroll
            for (int o = 16; o; o >>= 1) v += __shfl_xor_sync(0xffffffffu, v, o);
            if ((threadIdx.x & 31) == 0) sfin[threadIdx.x >> 5] = v;
        }
        __syncthreads();
        if (threadIdx.x == 0) {
            out[0] = (sfin[0] + sfin[1]) / (float)NPTS;
            g_cnt = 0;   // reset for next graph replay
        }
    }
}

extern "C" void kernel_launch(void* const* d_in, const int* in_sizes, int n_in,
                              void* d_out, int out_size) {
    const float* x   = (const float*)d_in[0];
    const int*   tgt = (const int*)d_in[1];
    float*       out = (float*)d_out;

    precompute_kernel<<<NPTS / 16, 256>>>(x);

    cudaFuncSetAttribute(tile_kernel,
                         cudaFuncAttributeMaxDynamicSharedMemorySize, SMEM_BYTES);
    tile_kernel<<<NCTAS, 256, SMEM_BYTES>>>(tgt);

    merge_kernel<<<NPTS / 128, 128>>>(out);
}

// round 12
// speedup vs baseline: 2.0555x; 1.1278x over previous
#include <cuda_runtime.h>
#include <cuda_fp16.h>
#include <cstdint>
#include <math.h>

// BatchHardTripletLoss: N=8192, D=128, fp32 in, scalar fp32 out.
// Gram on mma.sync fp16 (fp32 acc), single pass: dot = fp16(x)_i . fp16(x)_j
// Upper-triangle 128x128 tiles (2080 CTAs); dual fold per tile feeds
// per-anchor hardest-pos/neg directly via deterministic RED.MAX atomics:
//   hp: d2 clamped >= 0, raw bits, atomicMax (zero-init == "no positive -> 0")
//   hn: key = ~bits(-d2), atomicMax selects min d2; zero-init is identity.
// Min/max atomics are order-independent -> graph-replay deterministic and
// idempotent across replays. Merge pass is a trivial 8K-element reduction.
// 2 CTAs/SM (68.6KB smem); f32x2 FFMA2 packed epilogue arithmetic.

#define NPTS   8192
#define DIM    128
#define MARGIN 0.2f
#define EPSV   1e-6f
#define TILE   128
#define NCTAS  2080              // 64*65/2

// smem layout (bytes)
#define OFF_A    0               // 32 KB fp16 A tile
#define OFF_B    32768           // 32 KB fp16 B tile (scratch aliases after k-loop)
#define OFF_CJR  65536           // float2[128] row meta (cj, label)
#define OFF_CJC  66560           // float2[128] col meta
#define OFF_CIR  67584           // float[128] row ci
#define OFF_CIC  68096           // float[128] col ci
#define SMEM_BYTES 68608
#define SCR_STRIDE 18            // 16 groups + pad -> conflict-free
#define SCR_HN_OFF (128 * SCR_STRIDE * 4)   // 9216 B

__device__ float g_ci[NPTS];
__device__ float g_cj[NPTS];
__device__ __align__(16) __half g_xh[NPTS * DIM];
__device__ unsigned g_hpb[NPTS];   // zero-init: hp fallback 0
__device__ unsigned g_hnb[NPTS];   // zero-init: identity for ~bits(-d2) max-keys
__device__ float g_bsum[32];
__device__ int   g_cnt = 0;

// ---------------- helpers ----------------
__device__ __forceinline__ uint32_t smem_u32(const void* p) {
    uint32_t a;
    asm("{ .reg .u64 t; cvta.to.shared.u64 t, %1; cvt.u32.u64 %0, t; }" : "=r"(a) : "l"(p));
    return a;
}
__device__ __forceinline__ uint32_t t_off(int r, int c) {
    return (uint32_t)(((r >> 3) << 10) + ((c >> 3) << 14) + ((r & 7) << 7)
                      + (((c & 7) ^ (r & 7)) << 4));
}
__device__ __forceinline__ void cp16(uint32_t saddr, const void* gaddr) {
    asm volatile("cp.async.cg.shared.global [%0], [%1], 16;"
                 :: "r"(saddr), "l"(gaddr) : "memory");
}
__device__ __forceinline__ void ldsm4(uint32_t* r, uint32_t addr) {
    asm volatile("ldmatrix.sync.aligned.m8n8.x4.shared.b16 {%0,%1,%2,%3}, [%4];"
                 : "=r"(r[0]), "=r"(r[1]), "=r"(r[2]), "=r"(r[3]) : "r"(addr));
}
__device__ __forceinline__ void mma16816(float* c, const uint32_t* a, const uint32_t* b) {
    asm volatile("mma.sync.aligned.m16n8k16.row.col.f32.f16.f16.f32 "
                 "{%0,%1,%2,%3}, {%4,%5,%6,%7}, {%8,%9}, {%0,%1,%2,%3};"
                 : "+f"(c[0]), "+f"(c[1]), "+f"(c[2]), "+f"(c[3])
                 : "r"(a[0]), "r"(a[1]), "r"(a[2]), "r"(a[3]), "r"(b[0]), "r"(b[1]));
}
// packed f32x2 helpers (SASS FFMA2)
__device__ __forceinline__ uint64_t pack2(float lo, float hi) {
    uint64_t r;
    asm("mov.b64 %0, {%1, %2};" : "=l"(r) : "f"(lo), "f"(hi));
    return r;
}
__device__ __forceinline__ void unpack2(float& lo, float& hi, uint64_t v) {
    asm("mov.b64 {%0, %1}, %2;" : "=f"(lo), "=f"(hi) : "l"(v));
}
__device__ __forceinline__ uint64_t fma2(uint64_t a, uint64_t b, uint64_t c) {
    uint64_t d;
    asm("fma.rn.f32x2 %0, %1, %2, %3;" : "=l"(d) : "l"(a), "l"(b), "l"(c));
    return d;
}
// deterministic hardest-pos / hardest-neg atomics
__device__ __forceinline__ void red_hp(int r, float d2) {
    atomicMax(&g_hpb[r], __float_as_uint(fmaxf(d2, 0.0f)));
}
__device__ __forceinline__ void red_hn(int r, float d2) {
    atomicMax(&g_hnb[r], ~__float_as_uint(-fmaxf(d2, 0.0f)));
}
__device__ __forceinline__ int strip_base(int b) { return b * (129 - b) / 2; }

// ---------------- precompute: ci/cj + fp16 conversion (2 rows/warp) ------
__global__ void precompute_kernel(const float* __restrict__ x) {
    int w = (blockIdx.x * blockDim.x + threadIdx.x) >> 5;
    int lane = threadIdx.x & 31;
    int row0 = w * 2;
    float4 v0 = *(const float4*)(x + (size_t)row0 * DIM + lane * 4);
    float4 v1 = *(const float4*)(x + (size_t)(row0 + 1) * DIM + lane * 4);
    #pragma unroll
    for (int r = 0; r < 2; r++) {
        float4 v = r ? v1 : v0;
        int row = row0 + r;
        float sq = v.x * v.x + v.y * v.y + v.z * v.z + v.w * v.w;
        float s  = v.x + v.y + v.z + v.w;
        #pragma unroll
        for (int o = 16; o; o >>= 1) {
            sq += __shfl_xor_sync(0xffffffffu, sq, o);
            s  += __shfl_xor_sync(0xffffffffu, s,  o);
        }
        if (lane == 0) {
            g_ci[row] = sq - 2.0f * EPSV * s;
            g_cj[row] = sq + 2.0f * EPSV * s + (float)DIM * EPSV * EPSV;
        }
        __half2* dh = (__half2*)(g_xh + (size_t)row * DIM + lane * 4);
        dh[0] = __floats2half2_rn(v.x, v.y);
        dh[1] = __floats2half2_rn(v.z, v.w);
    }
}

// ---------------- main fused kernel: one triangle tile per CTA ----------
__global__ void __launch_bounds__(256, 2)
tile_kernel(const int* __restrict__ tgt) {
    extern __shared__ char smem[];
    const uint32_t sb = smem_u32(smem);
    const int tid  = threadIdx.x;
    const int lane = tid & 31;
    const int wid  = tid >> 5;
    const int wm = wid & 3;          // 4 warps over M (32 rows each)
    const int wn = wid >> 2;         // 2 warps over N (64 cols each)
    float2* scjr = (float2*)(smem + OFF_CJR);
    float2* scjc = (float2*)(smem + OFF_CJC);
    float*  scir = (float*)(smem + OFF_CIR);
    float*  scic = (float*)(smem + OFF_CIC);

    // (bi, bj) from linear upper-triangle index
    const int t = blockIdx.x;
    int bi = (int)(64.5f - sqrtf(64.5f * 64.5f - 2.0f * (float)t));
    if (bi < 0) bi = 0; if (bi > 63) bi = 63;
    while (bi < 63 && strip_base(bi + 1) <= t) bi++;
    while (bi > 0 && strip_base(bi) > t) bi--;
    const int bj = bi + (t - strip_base(bi));

    // stage A (32 KB) + B (32 KB) + meta
    {
        const char* ga = (const char*)(g_xh + (size_t)bi * TILE * DIM);
        const char* gb = (const char*)(g_xh + (size_t)bj * TILE * DIM);
        #pragma unroll
        for (int it = 0; it < 8; it++) {
            int lin = it * 256 + tid;
            uint32_t off = t_off(lin >> 4, lin & 15);
            cp16(sb + OFF_A + off, ga + (size_t)lin * 16);
            cp16(sb + OFF_B + off, gb + (size_t)lin * 16);
        }
        if (tid < TILE) {
            int r = bi * TILE + tid;
            int j = bj * TILE + tid;
            scjr[tid] = make_float2(g_cj[r], __int_as_float(tgt[r]));
            scjc[tid] = make_float2(g_cj[j], __int_as_float(tgt[j]));
            scir[tid] = g_ci[r];
            scic[tid] = g_ci[j];
        }
        asm volatile("cp.async.commit_group;" ::: "memory");
    }

    const int ra_lane = (lane & 15);
    const int ca_add  = (lane >> 4);
    const int rb_lane = ((lane >> 4) << 3) + (lane & 7);
    const int cb_add  = ((lane >> 3) & 1);

    asm volatile("cp.async.wait_group 0;" ::: "memory");
    __syncthreads();

    // ---------------- single-pass MMA over K=128 ----------------
    const uint32_t sA = sb + OFF_A, sB = sb + OFF_B;

    float acc[2][8][4];
    #pragma unroll
    for (int mt = 0; mt < 2; mt++)
        #pragma unroll
        for (int n8 = 0; n8 < 8; n8++)
            #pragma unroll
            for (int q = 0; q < 4; q++) acc[mt][n8][q] = 0.0f;

    #pragma unroll
    for (int ks = 0; ks < 8; ks++) {
        uint32_t ah[2][4], bh[4][4];
        #pragma unroll
        for (int mt = 0; mt < 2; mt++) {
            uint32_t off = t_off(wm * 32 + mt * 16 + ra_lane, 2 * ks + ca_add);
            ldsm4(ah[mt], sA + off);
        }
        #pragma unroll
        for (int nt = 0; nt < 4; nt++) {
            uint32_t off = t_off(wn * 64 + nt * 16 + rb_lane, 2 * ks + cb_add);
            ldsm4(bh[nt], sB + off);
        }
        #pragma unroll
        for (int mt = 0; mt < 2; mt++)
            #pragma unroll
            for (int nt = 0; nt < 4; nt++) {
                mma16816(acc[mt][2 * nt],     ah[mt], &bh[nt][0]);
                mma16816(acc[mt][2 * nt + 1], ah[mt], &bh[nt][2]);
            }
    }

    __syncthreads();   // all warps done with B before scratch aliasing

    // ---------------- dual-fold epilogue (packed f32x2) ----------------
    const uint64_t NEG2 = pack2(-2.0f, -2.0f);
    uint64_t cjr2[2][2];
    int      tir[2][2];
    float    cir[2][2];
    #pragma unroll
    for (int mt = 0; mt < 2; mt++)
        #pragma unroll
        for (int so = 0; so < 2; so++) {
            int rloc = wm * 32 + mt * 16 + so * 8 + (lane >> 2);
            float2 q = scjr[rloc];
            cjr2[mt][so] = pack2(q.x, q.x);
            tir[mt][so] = __float_as_int(q.y);
            cir[mt][so] = scir[rloc];
        }
    float hpr[2][2], hnr[2][2];
    #pragma unroll
    for (int mt = 0; mt < 2; mt++)
        #pragma unroll
        for (int so = 0; so < 2; so++) { hpr[mt][so] = -3.4e38f; hnr[mt][so] = 3.4e38f; }

    // col-fold scratch over dead B tile: [128 cols][18] per array
    float* scrHp = (float*)(smem + OFF_B);
    float* scrHn = (float*)(smem + OFF_B + SCR_HN_OFF);
    const int g16 = wm * 4 + (lane >> 3);          // group after 1-round shfl fold
    const bool keep = ((lane >> 2) & 1) == 0;

    #pragma unroll
    for (int n8 = 0; n8 < 8; n8++) {
        const int col0 = wn * 64 + n8 * 8 + (lane & 3) * 2;
        float2 qc0 = scjc[col0];
        float2 qc1 = scjc[col0 + 1];
        const uint64_t cjc2 = pack2(qc0.x, qc1.x);
        const int tj0 = __float_as_int(qc0.y);
        const int tj1 = __float_as_int(qc1.y);
        float hpc0 = -3.4e38f, hnc0 = 3.4e38f;
        float hpc1 = -3.4e38f, hnc1 = 3.4e38f;
        #pragma unroll
        for (int mt = 0; mt < 2; mt++)
            #pragma unroll
            for (int so = 0; so < 2; so++) {
                uint64_t accp = pack2(acc[mt][n8][so * 2], acc[mt][n8][so * 2 + 1]);
                uint64_t tvr2 = fma2(accp, NEG2, cjc2);          // (d0+cjc0, d1+cjc1)
                uint64_t tvc2 = fma2(accp, NEG2, cjr2[mt][so]);  // (d0+cjr,  d1+cjr)
                float r0, r1, c0, c1;
                unpack2(r0, r1, tvr2);
                unpack2(c0, c1, tvc2);
                if (tj0 == tir[mt][so]) { hpr[mt][so] = fmaxf(hpr[mt][so], r0); hpc0 = fmaxf(hpc0, c0); }
                else                    { hnr[mt][so] = fminf(hnr[mt][so], r0); hnc0 = fminf(hnc0, c0); }
                if (tj1 == tir[mt][so]) { hpr[mt][so] = fmaxf(hpr[mt][so], r1); hpc1 = fmaxf(hpc1, c1); }
                else                    { hnr[mt][so] = fminf(hnr[mt][so], r1); hnc1 = fminf(hnc1, c1); }
            }
        hpc0 = fmaxf(hpc0, __shfl_xor_sync(0xffffffffu, hpc0, 4));
        hnc0 = fminf(hnc0, __shfl_xor_sync(0xffffffffu, hnc0, 4));
        hpc1 = fmaxf(hpc1, __shfl_xor_sync(0xffffffffu, hpc1, 4));
        hnc1 = fminf(hnc1, __shfl_xor_sync(0xffffffffu, hnc1, 4));
        if (keep) {
            scrHp[col0 * SCR_STRIDE + g16] = hpc0;
            scrHn[col0 * SCR_STRIDE + g16] = hnc0;
            scrHp[(col0 + 1) * SCR_STRIDE + g16] = hpc1;
            scrHn[(col0 + 1) * SCR_STRIDE + g16] = hnc1;
        }
    }

    // row fold across the 4 column-lanes -> deterministic atomics
    #pragma unroll
    for (int o = 1; o <= 2; o <<= 1)
        #pragma unroll
        for (int mt = 0; mt < 2; mt++)
            #pragma unroll
            for (int so = 0; so < 2; so++) {
                hpr[mt][so] = fmaxf(hpr[mt][so], __shfl_xor_sync(0xffffffffu, hpr[mt][so], o));
                hnr[mt][so] = fminf(hnr[mt][so], __shfl_xor_sync(0xffffffffu, hnr[mt][so], o));
            }
    if ((lane & 3) == 0) {
        #pragma unroll
        for (int mt = 0; mt < 2; mt++)
            #pragma unroll
            for (int so = 0; so < 2; so++) {
                int r = bi * TILE + wm * 32 + mt * 16 + so * 8 + (lane >> 2);
                red_hp(r, cir[mt][so] + hpr[mt][so]);
                red_hn(r, cir[mt][so] + hnr[mt][so]);
            }
    }

    __syncthreads();   // scratch fully written

    // col fold: tid<128 folds hp for column tid; tid>=128 folds hn
    {
        int colL = tid & 127;
        int j = bj * TILE + colL;
        float ci_c = scic[colL];
        if (tid < 128) {
            float v = scrHp[colL * SCR_STRIDE];
            #pragma unroll
            for (int gq = 1; gq < 16; gq++) v = fmaxf(v, scrHp[colL * SCR_STRIDE + gq]);
            red_hp(j, ci_c + v);
        } else {
            float v = scrHn[colL * SCR_STRIDE];
            #pragma unroll
            for (int gq = 1; gq < 16; gq++) v = fminf(v, scrHn[colL * SCR_STRIDE + gq]);
            red_hn(j, ci_c + v);
        }
    }
}

// ---------------- merge: decode per-anchor hp/hn -> loss -> mean ---------
__global__ void merge_kernel(float* __restrict__ out) {
    __shared__ float ssum[256];
    __shared__ bool  last;
    int r = blockIdx.x * 256 + threadIdx.x;
    float hp = __uint_as_float(g_hpb[r]);            // >= 0 by construction
    float hn = -__uint_as_float(~g_hnb[r]);          // decode min-key
    float loss = fmaxf(sqrtf(hp) - sqrtf(hn) + MARGIN, 0.0f);
    ssum[threadIdx.x] = loss;
    __syncthreads();
    for (int o = 128; o; o >>= 1) {
        if (threadIdx.x < o) ssum[threadIdx.x] += ssum[threadIdx.x + o];
        __syncthreads();
    }
    if (threadIdx.x == 0) {
        g_bsum[blockIdx.x] = ssum[0];
        __threadfence();
        int prev = atomicAdd(&g_cnt, 1);
        last = (prev == gridDim.x - 1);
    }
    __syncthreads();
    if (last && threadIdx.x < 32) {
        float v = g_bsum[threadIdx.x];
        #pragma unroll
        for (int o = 16; o; o >>= 1) v += __shfl_xor_sync(0xffffffffu, v, o);
        if (threadIdx.x == 0) {
            out[0] = v / (float)NPTS;
            g_cnt = 0;   // reset for next graph replay
        }
    }
}

extern "C" void kernel_launch(void* const* d_in, const int* in_sizes, int n_in,
                              void* d_out, int out_size) {
    const float* x   = (const float*)d_in[0];
    const int*   tgt = (const int*)d_in[1];
    float*       out = (float*)d_out;

    precompute_kernel<<<NPTS / 16, 256>>>(x);

    cudaFuncSetAttribute(tile_kernel,
                         cudaFuncAttributeMaxDynamicSharedMemorySize, SMEM_BYTES);
    tile_kernel<<<NCTAS, 256, SMEM_BYTES>>>(tgt);

    merge_kernel<<<NPTS / 256, 256>>>(out);
}